// round 5
// baseline (speedup 1.0000x reference)
#include <cuda_runtime.h>
#include <math.h>

#define HEADS 8
#define DIM 64
#define DH 64
#define DK 24
#define DHK 3
#define B 4
#define H 128
#define W 128
#define NTOK (H*W)           // 16384

typedef unsigned long long ull;

// ---------------- scratch ---------------------------------------------------
// g_kinp is PLANAR: [b][ch][y][x]
__device__ float g_kinp[B * DK * H * W];     // 6.29 MB
__device__ float g_SW[2 * B * 24 * 64];      // [0..6143]=S  [6144..12287]=W2

// ---------------- packed f32x2 helpers -------------------------------------
__device__ __forceinline__ ull pack2(float lo, float hi) {
    ull r; asm("mov.b64 %0, {%1,%2};" : "=l"(r) : "f"(lo), "f"(hi)); return r;
}
__device__ __forceinline__ void unpack2(ull v, float& lo, float& hi) {
    asm("mov.b64 {%0,%1}, %2;" : "=f"(lo), "=f"(hi) : "l"(v));
}
__device__ __forceinline__ void fma2(ull& d, ull a, ull b) {
    asm("fma.rn.f32x2 %0, %1, %2, %0;" : "+l"(d) : "l"(a), "l"(b));
}

__device__ __forceinline__ float gelu_exact(float x) {
    return 0.5f * x * (1.0f + erff(x * 0.70710678118654752f));
}

// ===========================================================================
// K1: k_inp = illu_map @ Wk (planar write) + S[b] += k_inp^T @ x
// grid (128 rows, B) block 256; one block = one image row (128 tokens).
// x is read directly via LDG in the S loop (coalesced, L1-served, 8x reuse).
// ===========================================================================
__global__ __launch_bounds__(256, 4) void k1_kinp_S(
    const float* __restrict__ x, const float* __restrict__ im,
    const float* __restrict__ Wk)
{
    __shared__ __align__(16) float wk_s[576];
    __shared__ __align__(16) float im_s[128 * 25];
    __shared__ __align__(16) float k_s[128 * 25];

    const int tid = threadIdx.x;
    const int b = blockIdx.y;
    const int row = blockIdx.x;
    const int t0 = b * NTOK + row * 128;

    for (int i = tid; i < 576; i += 256) wk_s[i] = Wk[i];
    {
        const float* img = im + (size_t)t0 * 24;
        #pragma unroll
        for (int i = tid; i < 3072; i += 256) {
            int tok = i / 24, ci = i - tok * 24;
            im_s[tok * 25 + ci] = img[i];
        }
    }
    __syncthreads();

    // k_inp: 2 threads per token (each does 12 output channels)
    {
        const int tok = tid >> 1;
        const int j0 = (tid & 1) * 12;
        float acc[12];
        #pragma unroll
        for (int j = 0; j < 12; j++) acc[j] = 0.f;
        #pragma unroll 4
        for (int ci = 0; ci < 24; ci++) {
            float inv = im_s[tok * 25 + ci];
            const float4* wp4 = (const float4*)&wk_s[ci * 24 + j0];
            float4 w0 = wp4[0], w1 = wp4[1], w2 = wp4[2];
            acc[0] += inv * w0.x; acc[1] += inv * w0.y; acc[2] += inv * w0.z; acc[3] += inv * w0.w;
            acc[4] += inv * w1.x; acc[5] += inv * w1.y; acc[6] += inv * w1.z; acc[7] += inv * w1.w;
            acc[8] += inv * w2.x; acc[9] += inv * w2.y; acc[10] += inv * w2.z; acc[11] += inv * w2.w;
        }
        #pragma unroll
        for (int j = 0; j < 12; j++) k_s[tok * 25 + j0 + j] = acc[j];
    }
    __syncthreads();

    // write k_inp PLANAR: per channel 128 contiguous floats (coalesced)
    {
        #pragma unroll
        for (int i = tid; i < 3072; i += 256) {
            int ch = i >> 7, xx = i & 127;
            g_kinp[(((size_t)b * 24 + ch) * H + row) * W + xx] = k_s[xx * 25 + ch];
        }
    }

    // S partial: warp jj owns j = jj*3+{0,1,2}; lane cc owns c = cc*2+{0,1}
    {
        const int jj = tid >> 5;
        const int cc = tid & 31;
        ull s0 = 0, s1 = 0, s2 = 0;
        const float* xbase = x + (size_t)t0 * 64 + cc * 2;
        #pragma unroll 4
        for (int t = 0; t < 128; t++) {
            ull xv = *(const ull*)(xbase + t * 64);
            float ka = k_s[t * 25 + jj * 3 + 0];
            float kb = k_s[t * 25 + jj * 3 + 1];
            float kc = k_s[t * 25 + jj * 3 + 2];
            fma2(s0, pack2(ka, ka), xv);
            fma2(s1, pack2(kb, kb), xv);
            fma2(s2, pack2(kc, kc), xv);
        }
        float lo, hi;
        float* Sg = g_SW + b * 1536;
        unpack2(s0, lo, hi);
        atomicAdd(&Sg[(jj * 3 + 0) * 64 + cc * 2], lo);
        atomicAdd(&Sg[(jj * 3 + 0) * 64 + cc * 2 + 1], hi);
        unpack2(s1, lo, hi);
        atomicAdd(&Sg[(jj * 3 + 1) * 64 + cc * 2], lo);
        atomicAdd(&Sg[(jj * 3 + 1) * 64 + cc * 2 + 1], hi);
        unpack2(s2, lo, hi);
        atomicAdd(&Sg[(jj * 3 + 2) * 64 + cc * 2], lo);
        atomicAdd(&Sg[(jj * 3 + 2) * 64 + cc * 2 + 1], hi);
    }
}

// ===========================================================================
// K2: logits -> softmax -> M -> W2 (atomicAdd).  grid (2,B) block 256.
// ===========================================================================
__global__ __launch_bounds__(256) void k2_attn_W2(
    const float* __restrict__ Wq, const float* __restrict__ Wv,
    const float* __restrict__ Wp, const float* __restrict__ rescale)
{
    __shared__ float s_S[12 * 64];
    __shared__ float s_A[12 * 64];
    __shared__ float s_M[64 * 12];

    const int half = blockIdx.x;
    const int b = blockIdx.y;
    const int tid = threadIdx.x;

    const float* Sg = g_SW + b * 1536 + half * 12 * 64;
    for (int i = tid; i < 768; i += 256) s_S[i] = Sg[i];
    __syncthreads();

    const int jj = tid >> 6;
    const int d = tid & 63;
    const int h = half * 4 + jj;

    {
        float a0 = 0.f, a1 = 0.f, a2 = 0.f;
        const float* wqc = Wq + h * 64 + d;
        #pragma unroll 8
        for (int c = 0; c < 64; c++) {
            float wq = wqc[c * 512];
            a0 += s_S[(jj * 3 + 0) * 64 + c] * wq;
            a1 += s_S[(jj * 3 + 1) * 64 + c] * wq;
            a2 += s_S[(jj * 3 + 2) * 64 + c] * wq;
        }
        float sc = rescale[h] * 0.125f;
        s_A[(jj * 3 + 0) * 64 + d] = a0 * sc;
        s_A[(jj * 3 + 1) * 64 + d] = a1 * sc;
        s_A[(jj * 3 + 2) * 64 + d] = a2 * sc;
    }
    __syncthreads();

    {
        const int wid = tid >> 5, lane = tid & 31;
        for (int rowi = wid; rowi < 12; rowi += 8) {
            float v0 = s_A[rowi * 64 + lane];
            float v1 = s_A[rowi * 64 + 32 + lane];
            float m = fmaxf(v0, v1);
            #pragma unroll
            for (int off = 16; off; off >>= 1) m = fmaxf(m, __shfl_xor_sync(~0u, m, off));
            float e0 = __expf(v0 - m), e1 = __expf(v1 - m);
            float s = e0 + e1;
            #pragma unroll
            for (int off = 16; off; off >>= 1) s += __shfl_xor_sync(~0u, s, off);
            float inv = 1.0f / s;
            s_A[rowi * 64 + lane] = e0 * inv;
            s_A[rowi * 64 + 32 + lane] = e1 * inv;
        }
    }
    __syncthreads();

    {
        const int c = tid & 63;
        float m0 = 0.f, m1 = 0.f, m2 = 0.f;
        const float* wvr = Wv + c * 512 + h * 64;
        #pragma unroll 8
        for (int dd = 0; dd < 64; dd++) {
            float wv = wvr[dd];
            m0 += wv * s_A[(jj * 3 + 0) * 64 + dd];
            m1 += wv * s_A[(jj * 3 + 1) * 64 + dd];
            m2 += wv * s_A[(jj * 3 + 2) * 64 + dd];
        }
        s_M[c * 12 + jj * 3 + 0] = m0;
        s_M[c * 12 + jj * 3 + 1] = m1;
        s_M[c * 12 + jj * 3 + 2] = m2;
    }
    __syncthreads();

    {
        const int ce = tid >> 2;
        const int o0 = (tid & 3) * 6;
        float acc[6];
        #pragma unroll
        for (int u = 0; u < 6; u++) acc[u] = 0.f;
        #pragma unroll
        for (int jl = 0; jl < 12; jl++) {
            float m = s_M[ce * 12 + jl];
            int jjl = jl / 3, k = jl - jjl * 3;
            int j2 = k * 8 + half * 4 + jjl;
            const float* wp = Wp + j2 * 24 + o0;
            #pragma unroll
            for (int u = 0; u < 6; u++) acc[u] += m * wp[u];
        }
        float* W2g = g_SW + 6144 + b * 1536;
        #pragma unroll
        for (int u = 0; u < 6; u++) atomicAdd(&W2g[ce * 24 + o0 + u], acc[u]);
    }
}

// ===========================================================================
// K4: planar conv1 -> GELU -> conv2  +  projection fea@W2+bp, final write.
// grid (8,16,B) block 256, 16x8 output tile. 512 blocks, ~55KB smem,
// 4 blocks/SM, single balanced pass per phase.
// smem (floats): ws[1728](w1 then w2) W2q[1536] bps[32] kin[5760] t1[4800]
// kin region later reused for c2o [24][8][17]; t1 region reused for pp[128][25].
// ===========================================================================
#define S4_W 0
#define S4_W2Q 1728
#define S4_BP 3264
#define S4_KIN 3296
#define S4_T1 9056
#define K4_FLOATS (9056 + 4800)
#define K4_SMEM (K4_FLOATS * 4)

__global__ __launch_bounds__(256, 4) void k4_conv_proj(
    const float* __restrict__ fea, const float* __restrict__ bp,
    const float* __restrict__ c1w, const float* __restrict__ c2w,
    float* __restrict__ out)
{
    extern __shared__ __align__(16) float smem[];
    float* ws = smem + S4_W;      // conv weights (w1, then w2)
    float* W2q = smem + S4_W2Q;
    float* bps = smem + S4_BP;
    float* kin = smem + S4_KIN;   // planar [24][12][20]
    float* t1 = smem + S4_T1;     // planar [24][10][20]

    const int tid = threadIdx.x;
    const int b = blockIdx.z;
    const int gy0 = blockIdx.y * 8;
    const int gx0 = blockIdx.x * 16;

    for (int i = tid; i < 1728; i += 256) ws[i] = c1w[i];
    {
        const float* w2g = g_SW + 6144 + b * 1536;
        for (int i = tid; i < 1536; i += 256) W2q[i] = w2g[i];
    }
    if (tid < 24) bps[tid] = bp[tid];

    // stage kin planar, halo 12x20, zero-padded
    for (int idx = tid; idx < 5760; idx += 256) {
        int ch = idx / 240, rem = idx - ch * 240;
        int yy = rem / 20, xx = rem - yy * 20;
        int gy = gy0 - 2 + yy, gx = gx0 - 2 + xx;
        float v = 0.f;
        if ((unsigned)gy < (unsigned)H && (unsigned)gx < (unsigned)W)
            v = g_kinp[(((size_t)b * 24 + ch) * H + gy) * W + gx];
        kin[ch * 240 + yy * 20 + xx] = v;
    }
    __syncthreads();

    // conv1 + GELU -> t1 (zero outside image). unit = oc*10 + ry. 240 units.
    if (tid < 240) {
        int oc = tid / 10;
        int ry = tid - oc * 10;
        const float* kbase = kin + (oc >> 3) * (8 * 240) + ry * 20;
        float a[18];
        #pragma unroll
        for (int q = 0; q < 18; q++) a[q] = 0.f;
        #pragma unroll
        for (int i = 0; i < 8; i++) {
            const float* wr = ws + oc * 72 + i * 9;
            float wreg[9];
            #pragma unroll
            for (int q = 0; q < 9; q++) wreg[q] = wr[q];
            const float* r0 = kbase + i * 240;
            #pragma unroll
            for (int ky = 0; ky < 3; ky++) {
                const float4* rp = (const float4*)(r0 + ky * 20);
                float rr[20];
                #pragma unroll
                for (int q = 0; q < 5; q++) {
                    float4 f = rp[q];
                    rr[q * 4] = f.x; rr[q * 4 + 1] = f.y;
                    rr[q * 4 + 2] = f.z; rr[q * 4 + 3] = f.w;
                }
                float wa = wreg[ky * 3], wb = wreg[ky * 3 + 1], wc = wreg[ky * 3 + 2];
                #pragma unroll
                for (int xq = 0; xq < 18; xq++)
                    a[xq] += wa * rr[xq] + wb * rr[xq + 1] + wc * rr[xq + 2];
            }
        }
        int gy = gy0 - 1 + ry;
        bool rowin = (unsigned)gy < (unsigned)H;
        float* dst = t1 + oc * 200 + ry * 20;
        float v[18];
        #pragma unroll
        for (int xq = 0; xq < 18; xq++) {
            int gx = gx0 - 1 + xq;
            v[xq] = (rowin && (unsigned)gx < (unsigned)W) ? gelu_exact(a[xq]) : 0.f;
        }
        #pragma unroll
        for (int q = 0; q < 9; q++)
            *(ull*)(dst + 2 * q) = pack2(v[2 * q], v[2 * q + 1]);
    }
    __syncthreads();

    // swap in conv2 weights over the w1 region
    for (int i = tid; i < 1728; i += 256) ws[i] = c2w[i];
    __syncthreads();

    // conv2 -> c2o (reuse kin region): [24][8][17] padded. unit = oc*8 + ry.
    float* c2o = kin;
    if (tid < 192) {
        int oc = tid >> 3;
        int ry = tid & 7;
        const float* tbase = t1 + (oc >> 3) * (8 * 200) + ry * 20;
        float a[16];
        #pragma unroll
        for (int q = 0; q < 16; q++) a[q] = 0.f;
        #pragma unroll
        for (int i = 0; i < 8; i++) {
            const float* wr = ws + oc * 72 + i * 9;
            float wreg[9];
            #pragma unroll
            for (int q = 0; q < 9; q++) wreg[q] = wr[q];
            const float* r0 = tbase + i * 200;
            #pragma unroll
            for (int ky = 0; ky < 3; ky++) {
                const float4* rp = (const float4*)(r0 + ky * 20);
                float rr[20];
                #pragma unroll
                for (int q = 0; q < 5; q++) {
                    float4 f = rp[q];
                    rr[q * 4] = f.x; rr[q * 4 + 1] = f.y;
                    rr[q * 4 + 2] = f.z; rr[q * 4 + 3] = f.w;
                }
                float wa = wreg[ky * 3], wb = wreg[ky * 3 + 1], wc = wreg[ky * 3 + 2];
                #pragma unroll
                for (int xq = 0; xq < 16; xq++)
                    a[xq] += wa * rr[xq] + wb * rr[xq + 1] + wc * rr[xq + 2];
            }
        }
        float* dst = c2o + oc * 136 + ry * 17;
        #pragma unroll
        for (int q = 0; q < 16; q++) dst[q] = a[q];
    }
    __syncthreads();

    // projection: out = fea @ W2[b] + bp + c2o. 2 threads per pixel, split c.
    float* pp = t1;   // [128][25] partials from the upper half
    {
        const int half = tid >> 7;        // 0 or 1
        const int pxid = tid & 127;
        const int py = pxid >> 4, px = pxid & 15;
        ull acc[12];
        #pragma unroll
        for (int m = 0; m < 12; m++) acc[m] = 0ull;
        const float4* fea4 = (const float4*)(fea +
            ((size_t)b * NTOK + (size_t)(gy0 + py) * W + (gx0 + px)) * 64) + half * 8;
        #pragma unroll
        for (int c4 = 0; c4 < 8; c4++) {
            float4 f = fea4[c4];
            float fe[4] = {f.x, f.y, f.z, f.w};
            #pragma unroll
            for (int e = 0; e < 4; e++) {
                ull f2 = pack2(fe[e], fe[e]);
                const ulonglong2* wrow =
                    (const ulonglong2*)&W2q[((half * 8 + c4) * 4 + e) * 24];
                #pragma unroll
                for (int m = 0; m < 6; m++) {
                    ulonglong2 wp = wrow[m];
                    fma2(acc[2 * m], wp.x, f2);
                    fma2(acc[2 * m + 1], wp.y, f2);
                }
            }
        }
        if (half == 1) {
            float* dst = pp + pxid * 25;
            #pragma unroll
            for (int m = 0; m < 12; m++) {
                float lo, hi; unpack2(acc[m], lo, hi);
                dst[2 * m] = lo; dst[2 * m + 1] = hi;
            }
        }
        __syncthreads();
        if (half == 0) {
            const float* part = pp + pxid * 25;
            float res[24];
            #pragma unroll
            for (int m = 0; m < 12; m++) {
                float lo, hi; unpack2(acc[m], lo, hi);
                res[2 * m] = lo + part[2 * m] + bps[2 * m];
                res[2 * m + 1] = hi + part[2 * m + 1] + bps[2 * m + 1];
            }
            #pragma unroll
            for (int ch = 0; ch < 24; ch++)
                res[ch] += c2o[ch * 136 + py * 17 + px];
            float4* og = (float4*)(out +
                ((size_t)b * NTOK + (size_t)(gy0 + py) * W + (gx0 + px)) * 24);
            #pragma unroll
            for (int q = 0; q < 6; q++)
                og[q] = make_float4(res[q * 4], res[q * 4 + 1],
                                    res[q * 4 + 2], res[q * 4 + 3]);
        }
    }
}

// ===========================================================================
extern "C" void kernel_launch(void* const* d_in, const int* in_sizes, int n_in,
                              void* d_out, int out_size)
{
    const float* x = (const float*)d_in[0];
    const float* fea = (const float*)d_in[1];
    const float* im = (const float*)d_in[2];
    const float* Wq = (const float*)d_in[3];
    const float* Wk = (const float*)d_in[4];
    const float* Wv = (const float*)d_in[5];
    const float* rescale = (const float*)d_in[6];
    const float* Wp = (const float*)d_in[7];
    const float* bp = (const float*)d_in[8];
    const float* c1w = (const float*)d_in[9];
    const float* c2w = (const float*)d_in[10];
    float* out = (float*)d_out;

    void* swptr = nullptr;
    cudaGetSymbolAddress(&swptr, g_SW);
    cudaMemsetAsync(swptr, 0, sizeof(float) * 2 * B * 24 * 64, 0);

    cudaFuncSetAttribute(k4_conv_proj,
                         cudaFuncAttributeMaxDynamicSharedMemorySize, K4_SMEM);

    k1_kinp_S<<<dim3(128, B), 256>>>(x, im, Wk);
    k2_attn_W2<<<dim3(2, B), 256>>>(Wq, Wv, Wp, rescale);
    k4_conv_proj<<<dim3(8, 16, B), 256, K4_SMEM>>>(fea, bp, c1w, c2w, out);
}

// round 6
// speedup vs baseline: 1.0378x; 1.0378x over previous
#include <cuda_runtime.h>
#include <math.h>

#define HEADS 8
#define DIM 64
#define DH 64
#define DK 24
#define DHK 3
#define B 4
#define H 128
#define W 128
#define NTOK (H*W)           // 16384

typedef unsigned long long ull;

// ---------------- scratch ---------------------------------------------------
// g_kinp is PLANAR: [b][ch][y][x]
__device__ float g_kinp[B * DK * H * W];     // 6.29 MB
__device__ float g_SW[2 * B * 24 * 64];      // [0..6143]=S  [6144..12287]=W2

// ---------------- packed f32x2 helpers -------------------------------------
__device__ __forceinline__ ull pack2(float lo, float hi) {
    ull r; asm("mov.b64 %0, {%1,%2};" : "=l"(r) : "f"(lo), "f"(hi)); return r;
}
__device__ __forceinline__ void unpack2(ull v, float& lo, float& hi) {
    asm("mov.b64 {%0,%1}, %2;" : "=f"(lo), "=f"(hi) : "l"(v));
}
__device__ __forceinline__ void fma2(ull& d, ull a, ull b) {
    asm("fma.rn.f32x2 %0, %1, %2, %0;" : "+l"(d) : "l"(a), "l"(b));
}

__device__ __forceinline__ float gelu_exact(float x) {
    return 0.5f * x * (1.0f + erff(x * 0.70710678118654752f));
}

// dummy kernels: shift ncu's profiled launch (-s 5 -c 1) onto k4
__global__ void k0_dummy() {}

// ===========================================================================
// K1: k_inp = illu_map @ Wk (planar write) + S[b] += k_inp^T @ x
// grid (128 rows, B) block 256; one block = one image row (128 tokens).
// k stored in smem as splatted ull pairs (k,k) so the S loop needs no packs.
// dynamic smem layout (floats): wk[576] im[3200] x[8192] kd(ull)[3200]
// ===========================================================================
#define K1_WK 0
#define K1_IM 576
#define K1_X  3776
#define K1_KD 11968
#define K1_FLOATS (11968 + 6400)
#define K1_SMEM (K1_FLOATS * 4)

__global__ __launch_bounds__(256) void k1_kinp_S(
    const float* __restrict__ x, const float* __restrict__ im,
    const float* __restrict__ Wk)
{
    extern __shared__ __align__(16) float sm1[];
    float* wk_s = sm1 + K1_WK;
    float* im_s = sm1 + K1_IM;      // [128][25]
    float* x_s  = sm1 + K1_X;       // [128][64]
    ull*   k_d  = (ull*)(sm1 + K1_KD);  // [128][25] splatted pairs

    const int tid = threadIdx.x;
    const int b = blockIdx.y;
    const int row = blockIdx.x;
    const int t0 = b * NTOK + row * 128;

    for (int i = tid; i < 576; i += 256) wk_s[i] = Wk[i];
    {
        const float4* xg = (const float4*)(x + (size_t)t0 * 64);
        float4* xs4 = (float4*)x_s;
        #pragma unroll
        for (int i = tid; i < 2048; i += 256) xs4[i] = xg[i];
    }
    {
        const float* img = im + (size_t)t0 * 24;
        #pragma unroll
        for (int i = tid; i < 3072; i += 256) {
            int tok = i / 24, ci = i - tok * 24;
            im_s[tok * 25 + ci] = img[i];
        }
    }
    __syncthreads();

    // k_inp: 2 threads per token (each does 12 output channels); store splatted
    {
        const int tok = tid >> 1;
        const int j0 = (tid & 1) * 12;
        float acc[12];
        #pragma unroll
        for (int j = 0; j < 12; j++) acc[j] = 0.f;
        #pragma unroll 4
        for (int ci = 0; ci < 24; ci++) {
            float inv = im_s[tok * 25 + ci];
            const float4* wp4 = (const float4*)&wk_s[ci * 24 + j0];
            float4 w0 = wp4[0], w1 = wp4[1], w2 = wp4[2];
            acc[0] += inv * w0.x; acc[1] += inv * w0.y; acc[2] += inv * w0.z; acc[3] += inv * w0.w;
            acc[4] += inv * w1.x; acc[5] += inv * w1.y; acc[6] += inv * w1.z; acc[7] += inv * w1.w;
            acc[8] += inv * w2.x; acc[9] += inv * w2.y; acc[10] += inv * w2.z; acc[11] += inv * w2.w;
        }
        #pragma unroll
        for (int j = 0; j < 12; j++)
            k_d[tok * 25 + j0 + j] = pack2(acc[j], acc[j]);
    }
    __syncthreads();

    // write k_inp PLANAR (coalesced per channel); read lo half from k_d
    {
        const float* kdf = (const float*)k_d;
        #pragma unroll
        for (int i = tid; i < 3072; i += 256) {
            int ch = i >> 7, xx = i & 127;
            g_kinp[(((size_t)b * 24 + ch) * H + row) * W + xx] = kdf[(xx * 25 + ch) * 2];
        }
    }

    // S partial: warp jj owns j = jj*3+{0,1,2}; lane cc owns c = cc*2+{0,1}
    {
        const int jj = tid >> 5;
        const int cc = tid & 31;
        ull s0 = 0, s1 = 0, s2 = 0;
        const ull* xp = (const ull*)x_s;
        #pragma unroll 4
        for (int t = 0; t < 128; t++) {
            ull xv = xp[t * 32 + cc];
            ull ka = k_d[t * 25 + jj * 3 + 0];
            ull kb = k_d[t * 25 + jj * 3 + 1];
            ull kc = k_d[t * 25 + jj * 3 + 2];
            fma2(s0, ka, xv);
            fma2(s1, kb, xv);
            fma2(s2, kc, xv);
        }
        float lo, hi;
        float* Sg = g_SW + b * 1536;
        unpack2(s0, lo, hi);
        atomicAdd(&Sg[(jj * 3 + 0) * 64 + cc * 2], lo);
        atomicAdd(&Sg[(jj * 3 + 0) * 64 + cc * 2 + 1], hi);
        unpack2(s1, lo, hi);
        atomicAdd(&Sg[(jj * 3 + 1) * 64 + cc * 2], lo);
        atomicAdd(&Sg[(jj * 3 + 1) * 64 + cc * 2 + 1], hi);
        unpack2(s2, lo, hi);
        atomicAdd(&Sg[(jj * 3 + 2) * 64 + cc * 2], lo);
        atomicAdd(&Sg[(jj * 3 + 2) * 64 + cc * 2 + 1], hi);
    }
}

// ===========================================================================
// K2: logits -> softmax -> M -> W2 (atomicAdd).  grid (2,B) block 256.
// ===========================================================================
__global__ __launch_bounds__(256) void k2_attn_W2(
    const float* __restrict__ Wq, const float* __restrict__ Wv,
    const float* __restrict__ Wp, const float* __restrict__ rescale)
{
    __shared__ float s_S[12 * 64];
    __shared__ float s_A[12 * 64];
    __shared__ float s_M[64 * 12];

    const int half = blockIdx.x;
    const int b = blockIdx.y;
    const int tid = threadIdx.x;

    const float* Sg = g_SW + b * 1536 + half * 12 * 64;
    for (int i = tid; i < 768; i += 256) s_S[i] = Sg[i];
    __syncthreads();

    const int jj = tid >> 6;
    const int d = tid & 63;
    const int h = half * 4 + jj;

    {
        float a0 = 0.f, a1 = 0.f, a2 = 0.f;
        const float* wqc = Wq + h * 64 + d;
        #pragma unroll 8
        for (int c = 0; c < 64; c++) {
            float wq = wqc[c * 512];
            a0 += s_S[(jj * 3 + 0) * 64 + c] * wq;
            a1 += s_S[(jj * 3 + 1) * 64 + c] * wq;
            a2 += s_S[(jj * 3 + 2) * 64 + c] * wq;
        }
        float sc = rescale[h] * 0.125f;
        s_A[(jj * 3 + 0) * 64 + d] = a0 * sc;
        s_A[(jj * 3 + 1) * 64 + d] = a1 * sc;
        s_A[(jj * 3 + 2) * 64 + d] = a2 * sc;
    }
    __syncthreads();

    {
        const int wid = tid >> 5, lane = tid & 31;
        for (int rowi = wid; rowi < 12; rowi += 8) {
            float v0 = s_A[rowi * 64 + lane];
            float v1 = s_A[rowi * 64 + 32 + lane];
            float m = fmaxf(v0, v1);
            #pragma unroll
            for (int off = 16; off; off >>= 1) m = fmaxf(m, __shfl_xor_sync(~0u, m, off));
            float e0 = __expf(v0 - m), e1 = __expf(v1 - m);
            float s = e0 + e1;
            #pragma unroll
            for (int off = 16; off; off >>= 1) s += __shfl_xor_sync(~0u, s, off);
            float inv = 1.0f / s;
            s_A[rowi * 64 + lane] = e0 * inv;
            s_A[rowi * 64 + 32 + lane] = e1 * inv;
        }
    }
    __syncthreads();

    {
        const int c = tid & 63;
        float m0 = 0.f, m1 = 0.f, m2 = 0.f;
        const float* wvr = Wv + c * 512 + h * 64;
        #pragma unroll 8
        for (int dd = 0; dd < 64; dd++) {
            float wv = wvr[dd];
            m0 += wv * s_A[(jj * 3 + 0) * 64 + dd];
            m1 += wv * s_A[(jj * 3 + 1) * 64 + dd];
            m2 += wv * s_A[(jj * 3 + 2) * 64 + dd];
        }
        s_M[c * 12 + jj * 3 + 0] = m0;
        s_M[c * 12 + jj * 3 + 1] = m1;
        s_M[c * 12 + jj * 3 + 2] = m2;
    }
    __syncthreads();

    {
        const int ce = tid >> 2;
        const int o0 = (tid & 3) * 6;
        float acc[6];
        #pragma unroll
        for (int u = 0; u < 6; u++) acc[u] = 0.f;
        #pragma unroll
        for (int jl = 0; jl < 12; jl++) {
            float m = s_M[ce * 12 + jl];
            int jjl = jl / 3, k = jl - jjl * 3;
            int j2 = k * 8 + half * 4 + jjl;
            const float* wp = Wp + j2 * 24 + o0;
            #pragma unroll
            for (int u = 0; u < 6; u++) acc[u] += m * wp[u];
        }
        float* W2g = g_SW + 6144 + b * 1536;
        #pragma unroll
        for (int u = 0; u < 6; u++) atomicAdd(&W2g[ce * 24 + o0 + u], acc[u]);
    }
}

// ===========================================================================
// K4: oc-paired f32x2 conv1 -> GELU -> conv2  +  projection fea@W2+bp.
// grid (8,16,B) block 256, 16x8 output tile, 512 blocks, 55.4KB smem.
// Thread computes an output-channel PAIR via packed weight LDS.64 from the
// transposed weight layout ws[(i*9+r)*24 + oc], with splat-broadcast inputs.
// smem (floats): ws[1728] W2q[1536] bps[32] kin[24*12*20] t1[24*10*20]
// kin region reused for c2o [24][8][18]; t1 region reused for pp[128][25].
// ===========================================================================
#define S4_W 0
#define S4_W2Q 1728
#define S4_BP 3264
#define S4_KIN 3296
#define S4_T1 9056
#define K4_FLOATS (9056 + 4800)
#define K4_SMEM (K4_FLOATS * 4)

__global__ __launch_bounds__(256, 4) void k4_conv_proj(
    const float* __restrict__ fea, const float* __restrict__ bp,
    const float* __restrict__ c1w, const float* __restrict__ c2w,
    float* __restrict__ out)
{
    extern __shared__ __align__(16) float smem[];
    float* ws  = smem + S4_W;      // transposed conv weights [(i*9+r)*24 + oc]
    float* W2q = smem + S4_W2Q;
    float* bps = smem + S4_BP;
    float* kin = smem + S4_KIN;    // planar [24][12][20]
    float* t1  = smem + S4_T1;     // planar [24][10][20]

    const int tid = threadIdx.x;
    const int b = blockIdx.z;
    const int gy0 = blockIdx.y * 8;
    const int gx0 = blockIdx.x * 16;

    // stage conv1 weights transposed: src c1w[oc*72 + r2] -> ws[r2*24 + oc]
    for (int i = tid; i < 1728; i += 256) {
        int oc = i / 72, r2 = i - oc * 72;
        ws[r2 * 24 + oc] = c1w[i];
    }
    {
        const float* w2g = g_SW + 6144 + b * 1536;
        for (int i = tid; i < 1536; i += 256) W2q[i] = w2g[i];
    }
    if (tid < 24) bps[tid] = bp[tid];

    // stage kin planar, halo 12x20, zero-padded
    for (int idx = tid; idx < 5760; idx += 256) {
        int ch = idx / 240, rem = idx - ch * 240;
        int yy = rem / 20, xx = rem - yy * 20;
        int gy = gy0 - 2 + yy, gx = gx0 - 2 + xx;
        float v = 0.f;
        if ((unsigned)gy < (unsigned)H && (unsigned)gx < (unsigned)W)
            v = g_kinp[(((size_t)b * 24 + ch) * H + gy) * W + gx];
        kin[ch * 240 + yy * 20 + xx] = v;
    }
    __syncthreads();

    // conv1 + GELU -> t1.  240 units: ocp(12) x ry(10) x xh(2).
    // Each thread: oc pair (2*ocp, 2*ocp+1), 10 x-outputs (xh1 overlaps 2, skipped at store).
    if (tid < 240) {
        const int ocp = tid / 20;
        const int rem = tid - ocp * 20;
        const int ry  = rem >> 1;
        const int xh  = rem & 1;
        const int oc  = ocp * 2;
        const int g   = oc >> 3;
        const int in_off = xh << 3;
        const float* kb = kin + g * 1920 + ry * 20 + in_off;
        const float* wb = ws + oc;
        ull acc[10];
        #pragma unroll
        for (int m = 0; m < 10; m++) acc[m] = 0ull;
        #pragma unroll
        for (int i = 0; i < 8; i++) {
            const float* r0 = kb + i * 240;
            #pragma unroll
            for (int ky = 0; ky < 3; ky++) {
                const float4* rp = (const float4*)(r0 + ky * 20);
                float4 f0 = rp[0], f1 = rp[1], f2 = rp[2];
                float rr[12] = {f0.x, f0.y, f0.z, f0.w, f1.x, f1.y, f1.z, f1.w,
                                f2.x, f2.y, f2.z, f2.w};
                const float* wr = wb + (i * 9 + ky * 3) * 24;
                ull w0 = *(const ull*)(wr);
                ull w1 = *(const ull*)(wr + 24);
                ull w2 = *(const ull*)(wr + 48);
                ull sp = pack2(rr[0], rr[0]);
                ull sq = pack2(rr[1], rr[1]);
                #pragma unroll
                for (int o = 0; o < 10; o++) {
                    ull sr = pack2(rr[o + 2], rr[o + 2]);
                    fma2(acc[o], w0, sp);
                    fma2(acc[o], w1, sq);
                    fma2(acc[o], w2, sr);
                    sp = sq; sq = sr;
                }
            }
        }
        const int gy = gy0 - 1 + ry;
        const bool rowin = (unsigned)gy < (unsigned)H;
        float* d0 = t1 + oc * 200 + ry * 20;
        float* d1 = d0 + 200;
        const int olo = xh ? 2 : 0;   // xh1 skips its first 2 (owned by xh0)
        #pragma unroll
        for (int o = 0; o < 10; o++) {
            if (o < olo) continue;
            int xq = (xh << 3) + o;
            int gx = gx0 - 1 + xq;
            float lo, hi; unpack2(acc[o], lo, hi);
            bool inb = rowin && ((unsigned)gx < (unsigned)W);
            d0[xq] = inb ? gelu_exact(lo) : 0.f;
            d1[xq] = inb ? gelu_exact(hi) : 0.f;
        }
    }
    __syncthreads();

    // swap in conv2 weights (transposed) over the same region
    for (int i = tid; i < 1728; i += 256) {
        int oc = i / 72, r2 = i - oc * 72;
        ws[r2 * 24 + oc] = c2w[i];
    }
    __syncthreads();

    // conv2 -> c2o (kin region) [24][8][18].  192 units: ocp(12) x ry(8) x xh(2).
    float* c2o = kin;
    if (tid < 192) {
        const int ocp = tid / 16;
        const int rem = tid - ocp * 16;
        const int ry  = rem >> 1;
        const int xh  = rem & 1;
        const int oc  = ocp * 2;
        const int g   = oc >> 3;
        const int in_off = xh << 3;
        const float* tb = t1 + g * 1600 + ry * 20 + in_off;
        const float* wb = ws + oc;
        ull acc[8];
        #pragma unroll
        for (int m = 0; m < 8; m++) acc[m] = 0ull;
        #pragma unroll
        for (int i = 0; i < 8; i++) {
            const float* r0 = tb + i * 200;
            #pragma unroll
            for (int ky = 0; ky < 3; ky++) {
                const float4* rp = (const float4*)(r0 + ky * 20);
                float4 f0 = rp[0], f1 = rp[1], f2 = rp[2];
                float rr[12] = {f0.x, f0.y, f0.z, f0.w, f1.x, f1.y, f1.z, f1.w,
                                f2.x, f2.y, f2.z, f2.w};
                const float* wr = wb + (i * 9 + ky * 3) * 24;
                ull w0 = *(const ull*)(wr);
                ull w1 = *(const ull*)(wr + 24);
                ull w2 = *(const ull*)(wr + 48);
                ull sp = pack2(rr[0], rr[0]);
                ull sq = pack2(rr[1], rr[1]);
                #pragma unroll
                for (int o = 0; o < 8; o++) {
                    ull sr = pack2(rr[o + 2], rr[o + 2]);
                    fma2(acc[o], w0, sp);
                    fma2(acc[o], w1, sq);
                    fma2(acc[o], w2, sr);
                    sp = sq; sq = sr;
                }
            }
        }
        float* e0 = c2o + oc * 144 + ry * 18;
        float* e1 = e0 + 144;
        #pragma unroll
        for (int o = 0; o < 8; o++) {
            int xq = in_off + o;
            float lo, hi; unpack2(acc[o], lo, hi);
            e0[xq] = lo;
            e1[xq] = hi;
        }
    }
    __syncthreads();

    // projection: out = fea @ W2[b] + bp + c2o. 2 threads per pixel, split c.
    float* pp = t1;   // [128][25] partials from the upper half
    {
        const int half = tid >> 7;        // 0 or 1
        const int pxid = tid & 127;
        const int py = pxid >> 4, px = pxid & 15;
        ull acc[12];
        #pragma unroll
        for (int m = 0; m < 12; m++) acc[m] = 0ull;
        const float4* fea4 = (const float4*)(fea +
            ((size_t)b * NTOK + (size_t)(gy0 + py) * W + (gx0 + px)) * 64) + half * 8;
        #pragma unroll
        for (int c4 = 0; c4 < 8; c4++) {
            float4 f = fea4[c4];
            float fe[4] = {f.x, f.y, f.z, f.w};
            #pragma unroll
            for (int e = 0; e < 4; e++) {
                ull f2 = pack2(fe[e], fe[e]);
                const ulonglong2* wrow =
                    (const ulonglong2*)&W2q[((half * 8 + c4) * 4 + e) * 24];
                #pragma unroll
                for (int m = 0; m < 6; m++) {
                    ulonglong2 wp = wrow[m];
                    fma2(acc[2 * m], wp.x, f2);
                    fma2(acc[2 * m + 1], wp.y, f2);
                }
            }
        }
        if (half == 1) {
            float* dst = pp + pxid * 25;
            #pragma unroll
            for (int m = 0; m < 12; m++) {
                float lo, hi; unpack2(acc[m], lo, hi);
                dst[2 * m] = lo; dst[2 * m + 1] = hi;
            }
        }
        __syncthreads();
        if (half == 0) {
            const float* part = pp + pxid * 25;
            float res[24];
            #pragma unroll
            for (int m = 0; m < 12; m++) {
                float lo, hi; unpack2(acc[m], lo, hi);
                res[2 * m] = lo + part[2 * m] + bps[2 * m];
                res[2 * m + 1] = hi + part[2 * m + 1] + bps[2 * m + 1];
            }
            #pragma unroll
            for (int ch = 0; ch < 24; ch++)
                res[ch] += c2o[ch * 144 + py * 18 + px];
            float4* og = (float4*)(out +
                ((size_t)b * NTOK + (size_t)(gy0 + py) * W + (gx0 + px)) * 24);
            #pragma unroll
            for (int q = 0; q < 6; q++)
                og[q] = make_float4(res[q * 4], res[q * 4 + 1],
                                    res[q * 4 + 2], res[q * 4 + 3]);
        }
    }
}

// ===========================================================================
extern "C" void kernel_launch(void* const* d_in, const int* in_sizes, int n_in,
                              void* d_out, int out_size)
{
    const float* x = (const float*)d_in[0];
    const float* fea = (const float*)d_in[1];
    const float* im = (const float*)d_in[2];
    const float* Wq = (const float*)d_in[3];
    const float* Wk = (const float*)d_in[4];
    const float* Wv = (const float*)d_in[5];
    const float* rescale = (const float*)d_in[6];
    const float* Wp = (const float*)d_in[7];
    const float* bp = (const float*)d_in[8];
    const float* c1w = (const float*)d_in[9];
    const float* c2w = (const float*)d_in[10];
    float* out = (float*)d_out;

    cudaFuncSetAttribute(k1_kinp_S,
                         cudaFuncAttributeMaxDynamicSharedMemorySize, K1_SMEM);
    cudaFuncSetAttribute(k4_conv_proj,
                         cudaFuncAttributeMaxDynamicSharedMemorySize, K4_SMEM);

    // two no-op launches so ncu (-s 5 -c 1) profiles k4
    k0_dummy<<<1, 32>>>();
    k0_dummy<<<1, 32>>>();

    void* swptr = nullptr;
    cudaGetSymbolAddress(&swptr, g_SW);
    cudaMemsetAsync(swptr, 0, sizeof(float) * 2 * B * 24 * 64, 0);

    k1_kinp_S<<<dim3(128, B), 256, K1_SMEM>>>(x, im, Wk);
    k2_attn_W2<<<dim3(2, B), 256>>>(Wq, Wv, Wp, rescale);
    k4_conv_proj<<<dim3(8, 16, B), 256, K4_SMEM>>>(fea, bp, c1w, c2w, out);
}

// round 7
// speedup vs baseline: 1.1580x; 1.1158x over previous
#include <cuda_runtime.h>
#include <math.h>

#define HEADS 8
#define DIM 64
#define DH 64
#define DK 24
#define DHK 3
#define B 4
#define H 128
#define W 128
#define NTOK (H*W)           // 16384

typedef unsigned long long ull;

// ---------------- scratch ---------------------------------------------------
// g_kinp is PLANAR: [b][ch][y][x]
__device__ float g_kinp[B * DK * H * W];     // 6.29 MB
__device__ float g_SW[2 * B * 24 * 64];      // [0..6143]=S  [6144..12287]=W2

// ---------------- packed f32x2 helpers -------------------------------------
__device__ __forceinline__ ull pack2(float lo, float hi) {
    ull r; asm("mov.b64 %0, {%1,%2};" : "=l"(r) : "f"(lo), "f"(hi)); return r;
}
__device__ __forceinline__ void unpack2(ull v, float& lo, float& hi) {
    asm("mov.b64 {%0,%1}, %2;" : "=f"(lo), "=f"(hi) : "l"(v));
}
__device__ __forceinline__ void fma2(ull& d, ull a, ull b) {
    asm("fma.rn.f32x2 %0, %1, %2, %0;" : "+l"(d) : "l"(a), "l"(b));
}

__device__ __forceinline__ float gelu_exact(float x) {
    return 0.5f * x * (1.0f + erff(x * 0.70710678118654752f));
}

// ===========================================================================
// K1: k_inp = illu_map @ Wk (planar write) + S[b] += k_inp^T @ x
// grid (128 rows, B) block 256; one block = one image row (128 tokens).
// buf (32KB) holds im during phase A, then x during phase B -> 47.9KB smem,
// 4 blocks/SM, 512 blocks in a single wave.
// ===========================================================================
__global__ __launch_bounds__(256, 4) void k1_kinp_S(
    const float* __restrict__ x, const float* __restrict__ im,
    const float* __restrict__ Wk)
{
    __shared__ __align__(16) float wk_s[576];
    __shared__ __align__(16) float k_s[128 * 25];
    __shared__ __align__(16) float buf[128 * 64];   // im_s then x_s

    const int tid = threadIdx.x;
    const int b = blockIdx.y;
    const int row = blockIdx.x;
    const int t0 = b * NTOK + row * 128;

    for (int i = tid; i < 576; i += 256) wk_s[i] = Wk[i];
    {
        const float* img = im + (size_t)t0 * 24;
        #pragma unroll
        for (int i = tid; i < 3072; i += 256) {
            int tok = i / 24, ci = i - tok * 24;
            buf[tok * 25 + ci] = img[i];
        }
    }
    __syncthreads();

    // k_inp: 2 threads per token (each does 12 output channels)
    {
        const int tok = tid >> 1;
        const int j0 = (tid & 1) * 12;
        float acc[12];
        #pragma unroll
        for (int j = 0; j < 12; j++) acc[j] = 0.f;
        #pragma unroll 4
        for (int ci = 0; ci < 24; ci++) {
            float inv = buf[tok * 25 + ci];
            const float4* wp4 = (const float4*)&wk_s[ci * 24 + j0];
            float4 w0 = wp4[0], w1 = wp4[1], w2 = wp4[2];
            acc[0] += inv * w0.x; acc[1] += inv * w0.y; acc[2] += inv * w0.z; acc[3] += inv * w0.w;
            acc[4] += inv * w1.x; acc[5] += inv * w1.y; acc[6] += inv * w1.z; acc[7] += inv * w1.w;
            acc[8] += inv * w2.x; acc[9] += inv * w2.y; acc[10] += inv * w2.z; acc[11] += inv * w2.w;
        }
        #pragma unroll
        for (int j = 0; j < 12; j++) k_s[tok * 25 + j0 + j] = acc[j];
    }
    __syncthreads();

    // stage x into buf (overwrites im) + write k_inp PLANAR (coalesced)
    {
        const float4* xg = (const float4*)(x + (size_t)t0 * 64);
        float4* xs4 = (float4*)buf;
        #pragma unroll
        for (int i = tid; i < 2048; i += 256) xs4[i] = xg[i];
    }
    {
        #pragma unroll
        for (int i = tid; i < 3072; i += 256) {
            int ch = i >> 7, xx = i & 127;
            g_kinp[(((size_t)b * 24 + ch) * H + row) * W + xx] = k_s[xx * 25 + ch];
        }
    }
    __syncthreads();

    // S partial: warp jj owns j = jj*3+{0,1,2}; lane cc owns c = cc*2+{0,1}
    {
        const int jj = tid >> 5;
        const int cc = tid & 31;
        ull s0 = 0, s1 = 0, s2 = 0;
        const ull* xp = (const ull*)buf;
        #pragma unroll 4
        for (int t = 0; t < 128; t++) {
            ull xv = xp[t * 32 + cc];
            float ka = k_s[t * 25 + jj * 3 + 0];
            float kb = k_s[t * 25 + jj * 3 + 1];
            float kc = k_s[t * 25 + jj * 3 + 2];
            fma2(s0, pack2(ka, ka), xv);
            fma2(s1, pack2(kb, kb), xv);
            fma2(s2, pack2(kc, kc), xv);
        }
        float lo, hi;
        float* Sg = g_SW + b * 1536;
        unpack2(s0, lo, hi);
        atomicAdd(&Sg[(jj * 3 + 0) * 64 + cc * 2], lo);
        atomicAdd(&Sg[(jj * 3 + 0) * 64 + cc * 2 + 1], hi);
        unpack2(s1, lo, hi);
        atomicAdd(&Sg[(jj * 3 + 1) * 64 + cc * 2], lo);
        atomicAdd(&Sg[(jj * 3 + 1) * 64 + cc * 2 + 1], hi);
        unpack2(s2, lo, hi);
        atomicAdd(&Sg[(jj * 3 + 2) * 64 + cc * 2], lo);
        atomicAdd(&Sg[(jj * 3 + 2) * 64 + cc * 2 + 1], hi);
    }
}

// ===========================================================================
// K2: per-head attention + W2. grid (8) = heads, block 256, all 4 batches.
// Wq/Wv column slices staged into smem with COALESCED loads (stride-65 pad),
// killing the 31us latency stall of the strided per-thread version.
// ===========================================================================
__global__ __launch_bounds__(256) void k2_attn_W2(
    const float* __restrict__ Wq, const float* __restrict__ Wv,
    const float* __restrict__ Wp, const float* __restrict__ rescale)
{
    __shared__ __align__(16) float wqv_s[64 * 65];  // Wq slice, later Wv slice
    __shared__ float s_S[4 * 3 * 64];   // [b][k][c]
    __shared__ float s_A[4 * 3 * 64];   // [b][k][d]
    __shared__ float s_M[4 * 64 * 3];   // [(b*64+c)*3 + k]
    __shared__ float wp_s[3 * 24];

    const int h = blockIdx.x;
    const int tid = threadIdx.x;

    // stage Wq slice [c][d] (coalesced rows)
    for (int i = tid; i < 4096; i += 256) {
        int c = i >> 6, d = i & 63;
        wqv_s[c * 65 + d] = Wq[c * 512 + h * 64 + d];
    }
    // stage S rows (h*3 .. h*3+2) for all b
    for (int i = tid; i < 768; i += 256) {
        int b = i / 192, rem = i - b * 192;        // rem = k*64 + c
        s_S[i] = g_SW[b * 1536 + h * 3 * 64 + rem];
    }
    if (tid < 72) {
        int k = tid / 24, o = tid - k * 24;
        wp_s[tid] = Wp[(k * 8 + h) * 24 + o];
    }
    __syncthreads();

    const int b = tid >> 6;
    const int d = tid & 63;
    const float sc = rescale[h] * 0.125f;

    // logits: attn[b][k][d] = sum_c S[b][k][c] * Wq[c][h*64+d]
    {
        float a0 = 0.f, a1 = 0.f, a2 = 0.f;
        const float* Sb = s_S + b * 192;
        #pragma unroll 8
        for (int c = 0; c < 64; c++) {
            float wq = wqv_s[c * 65 + d];
            a0 += Sb[c] * wq;
            a1 += Sb[64 + c] * wq;
            a2 += Sb[128 + c] * wq;
        }
        s_A[(b * 3 + 0) * 64 + d] = a0 * sc;
        s_A[(b * 3 + 1) * 64 + d] = a1 * sc;
        s_A[(b * 3 + 2) * 64 + d] = a2 * sc;
    }
    __syncthreads();

    // softmax over d for the 12 (b,k) rows; one warp per row
    {
        const int wid = tid >> 5, lane = tid & 31;
        for (int rowi = wid; rowi < 12; rowi += 8) {
            float v0 = s_A[rowi * 64 + lane];
            float v1 = s_A[rowi * 64 + 32 + lane];
            float m = fmaxf(v0, v1);
            #pragma unroll
            for (int off = 16; off; off >>= 1) m = fmaxf(m, __shfl_xor_sync(~0u, m, off));
            float e0 = __expf(v0 - m), e1 = __expf(v1 - m);
            float s = e0 + e1;
            #pragma unroll
            for (int off = 16; off; off >>= 1) s += __shfl_xor_sync(~0u, s, off);
            float inv = 1.0f / s;
            s_A[rowi * 64 + lane] = e0 * inv;
            s_A[rowi * 64 + 32 + lane] = e1 * inv;
        }
    }
    __syncthreads();

    // re-stage Wv slice over the Wq region (coalesced)
    for (int i = tid; i < 4096; i += 256) {
        int c = i >> 6, dd = i & 63;
        wqv_s[c * 65 + dd] = Wv[c * 512 + h * 64 + dd];
    }
    __syncthreads();

    // M[b][c][k] = sum_d Wv[c][h*64+d] * attn[b][k][d]
    {
        const int c = tid & 63;          // b = tid>>6 (as above)
        float m0 = 0.f, m1 = 0.f, m2 = 0.f;
        const float* Ab = s_A + b * 192;
        const float* wvr = wqv_s + c * 65;
        #pragma unroll 8
        for (int dd = 0; dd < 64; dd++) {
            float wv = wvr[dd];
            m0 += wv * Ab[dd];
            m1 += wv * Ab[64 + dd];
            m2 += wv * Ab[128 + dd];
        }
        s_M[(b * 64 + c) * 3 + 0] = m0;
        s_M[(b * 64 + c) * 3 + 1] = m1;
        s_M[(b * 64 + c) * 3 + 2] = m2;
    }
    __syncthreads();

    // W2[b][c][o] += sum_k M[b][c][k] * Wp[k*8+h][o]
    {
        const int c = tid & 63;
        const float* mrow = &s_M[(b * 64 + c) * 3];
        float m0 = mrow[0], m1 = mrow[1], m2 = mrow[2];
        float* W2g = g_SW + 6144 + b * 1536 + c * 24;
        #pragma unroll
        for (int o = 0; o < 24; o++) {
            float v = m0 * wp_s[o] + m1 * wp_s[24 + o] + m2 * wp_s[48 + o];
            atomicAdd(&W2g[o], v);
        }
    }
}

// ===========================================================================
// K4: oc-paired f32x2 conv1 -> GELU -> conv2  +  projection fea@W2+bp.
// grid (8,16,B) block 256, 16x8 output tile, 512 blocks, 55.4KB smem.
// ===========================================================================
#define S4_W 0
#define S4_W2Q 1728
#define S4_BP 3264
#define S4_KIN 3296
#define S4_T1 9056
#define K4_FLOATS (9056 + 4800)
#define K4_SMEM (K4_FLOATS * 4)

__global__ __launch_bounds__(256, 4) void k4_conv_proj(
    const float* __restrict__ fea, const float* __restrict__ bp,
    const float* __restrict__ c1w, const float* __restrict__ c2w,
    float* __restrict__ out)
{
    extern __shared__ __align__(16) float smem[];
    float* ws  = smem + S4_W;      // transposed conv weights [(i*9+r)*24 + oc]
    float* W2q = smem + S4_W2Q;
    float* bps = smem + S4_BP;
    float* kin = smem + S4_KIN;    // planar [24][12][20]
    float* t1  = smem + S4_T1;     // planar [24][10][20]

    const int tid = threadIdx.x;
    const int b = blockIdx.z;
    const int gy0 = blockIdx.y * 8;
    const int gx0 = blockIdx.x * 16;

    for (int i = tid; i < 1728; i += 256) {
        int oc = i / 72, r2 = i - oc * 72;
        ws[r2 * 24 + oc] = c1w[i];
    }
    {
        const float* w2g = g_SW + 6144 + b * 1536;
        for (int i = tid; i < 1536; i += 256) W2q[i] = w2g[i];
    }
    if (tid < 24) bps[tid] = bp[tid];

    for (int idx = tid; idx < 5760; idx += 256) {
        int ch = idx / 240, rem = idx - ch * 240;
        int yy = rem / 20, xx = rem - yy * 20;
        int gy = gy0 - 2 + yy, gx = gx0 - 2 + xx;
        float v = 0.f;
        if ((unsigned)gy < (unsigned)H && (unsigned)gx < (unsigned)W)
            v = g_kinp[(((size_t)b * 24 + ch) * H + gy) * W + gx];
        kin[ch * 240 + yy * 20 + xx] = v;
    }
    __syncthreads();

    // conv1 + GELU -> t1.  240 units: ocp(12) x ry(10) x xh(2).
    if (tid < 240) {
        const int ocp = tid / 20;
        const int rem = tid - ocp * 20;
        const int ry  = rem >> 1;
        const int xh  = rem & 1;
        const int oc  = ocp * 2;
        const int g   = oc >> 3;
        const int in_off = xh << 3;
        const float* kb = kin + g * 1920 + ry * 20 + in_off;
        const float* wb = ws + oc;
        ull acc[10];
        #pragma unroll
        for (int m = 0; m < 10; m++) acc[m] = 0ull;
        #pragma unroll
        for (int i = 0; i < 8; i++) {
            const float* r0 = kb + i * 240;
            #pragma unroll
            for (int ky = 0; ky < 3; ky++) {
                const float4* rp = (const float4*)(r0 + ky * 20);
                float4 f0 = rp[0], f1 = rp[1], f2 = rp[2];
                float rr[12] = {f0.x, f0.y, f0.z, f0.w, f1.x, f1.y, f1.z, f1.w,
                                f2.x, f2.y, f2.z, f2.w};
                const float* wr = wb + (i * 9 + ky * 3) * 24;
                ull w0 = *(const ull*)(wr);
                ull w1 = *(const ull*)(wr + 24);
                ull w2 = *(const ull*)(wr + 48);
                ull sp = pack2(rr[0], rr[0]);
                ull sq = pack2(rr[1], rr[1]);
                #pragma unroll
                for (int o = 0; o < 10; o++) {
                    ull sr = pack2(rr[o + 2], rr[o + 2]);
                    fma2(acc[o], w0, sp);
                    fma2(acc[o], w1, sq);
                    fma2(acc[o], w2, sr);
                    sp = sq; sq = sr;
                }
            }
        }
        const int gy = gy0 - 1 + ry;
        const bool rowin = (unsigned)gy < (unsigned)H;
        float* d0 = t1 + oc * 200 + ry * 20;
        float* d1 = d0 + 200;
        const int olo = xh ? 2 : 0;
        #pragma unroll
        for (int o = 0; o < 10; o++) {
            if (o < olo) continue;
            int xq = (xh << 3) + o;
            int gx = gx0 - 1 + xq;
            float lo, hi; unpack2(acc[o], lo, hi);
            bool inb = rowin && ((unsigned)gx < (unsigned)W);
            d0[xq] = inb ? gelu_exact(lo) : 0.f;
            d1[xq] = inb ? gelu_exact(hi) : 0.f;
        }
    }
    __syncthreads();

    for (int i = tid; i < 1728; i += 256) {
        int oc = i / 72, r2 = i - oc * 72;
        ws[r2 * 24 + oc] = c2w[i];
    }
    __syncthreads();

    // conv2 -> c2o (kin region) [24][8][18].  192 units.
    float* c2o = kin;
    if (tid < 192) {
        const int ocp = tid / 16;
        const int rem = tid - ocp * 16;
        const int ry  = rem >> 1;
        const int xh  = rem & 1;
        const int oc  = ocp * 2;
        const int g   = oc >> 3;
        const int in_off = xh << 3;
        const float* tb = t1 + g * 1600 + ry * 20 + in_off;
        const float* wb = ws + oc;
        ull acc[8];
        #pragma unroll
        for (int m = 0; m < 8; m++) acc[m] = 0ull;
        #pragma unroll
        for (int i = 0; i < 8; i++) {
            const float* r0 = tb + i * 200;
            #pragma unroll
            for (int ky = 0; ky < 3; ky++) {
                const float4* rp = (const float4*)(r0 + ky * 20);
                float4 f0 = rp[0], f1 = rp[1], f2 = rp[2];
                float rr[12] = {f0.x, f0.y, f0.z, f0.w, f1.x, f1.y, f1.z, f1.w,
                                f2.x, f2.y, f2.z, f2.w};
                const float* wr = wb + (i * 9 + ky * 3) * 24;
                ull w0 = *(const ull*)(wr);
                ull w1 = *(const ull*)(wr + 24);
                ull w2 = *(const ull*)(wr + 48);
                ull sp = pack2(rr[0], rr[0]);
                ull sq = pack2(rr[1], rr[1]);
                #pragma unroll
                for (int o = 0; o < 8; o++) {
                    ull sr = pack2(rr[o + 2], rr[o + 2]);
                    fma2(acc[o], w0, sp);
                    fma2(acc[o], w1, sq);
                    fma2(acc[o], w2, sr);
                    sp = sq; sq = sr;
                }
            }
        }
        float* e0 = c2o + oc * 144 + ry * 18;
        float* e1 = e0 + 144;
        #pragma unroll
        for (int o = 0; o < 8; o++) {
            int xq = in_off + o;
            float lo, hi; unpack2(acc[o], lo, hi);
            e0[xq] = lo;
            e1[xq] = hi;
        }
    }
    __syncthreads();

    // projection: out = fea @ W2[b] + bp + c2o. 2 threads per pixel, split c.
    float* pp = t1;
    {
        const int half = tid >> 7;
        const int pxid = tid & 127;
        const int py = pxid >> 4, px = pxid & 15;
        ull acc[12];
        #pragma unroll
        for (int m = 0; m < 12; m++) acc[m] = 0ull;
        const float4* fea4 = (const float4*)(fea +
            ((size_t)b * NTOK + (size_t)(gy0 + py) * W + (gx0 + px)) * 64) + half * 8;
        #pragma unroll
        for (int c4 = 0; c4 < 8; c4++) {
            float4 f = fea4[c4];
            float fe[4] = {f.x, f.y, f.z, f.w};
            #pragma unroll
            for (int e = 0; e < 4; e++) {
                ull f2 = pack2(fe[e], fe[e]);
                const ulonglong2* wrow =
                    (const ulonglong2*)&W2q[((half * 8 + c4) * 4 + e) * 24];
                #pragma unroll
                for (int m = 0; m < 6; m++) {
                    ulonglong2 wp = wrow[m];
                    fma2(acc[2 * m], wp.x, f2);
                    fma2(acc[2 * m + 1], wp.y, f2);
                }
            }
        }
        if (half == 1) {
            float* dst = pp + pxid * 25;
            #pragma unroll
            for (int m = 0; m < 12; m++) {
                float lo, hi; unpack2(acc[m], lo, hi);
                dst[2 * m] = lo; dst[2 * m + 1] = hi;
            }
        }
        __syncthreads();
        if (half == 0) {
            const float* part = pp + pxid * 25;
            float res[24];
            #pragma unroll
            for (int m = 0; m < 12; m++) {
                float lo, hi; unpack2(acc[m], lo, hi);
                res[2 * m] = lo + part[2 * m] + bps[2 * m];
                res[2 * m + 1] = hi + part[2 * m + 1] + bps[2 * m + 1];
            }
            #pragma unroll
            for (int ch = 0; ch < 24; ch++)
                res[ch] += c2o[ch * 144 + py * 18 + px];
            float4* og = (float4*)(out +
                ((size_t)b * NTOK + (size_t)(gy0 + py) * W + (gx0 + px)) * 24);
            #pragma unroll
            for (int q = 0; q < 6; q++)
                og[q] = make_float4(res[q * 4], res[q * 4 + 1],
                                    res[q * 4 + 2], res[q * 4 + 3]);
        }
    }
}

// ===========================================================================
extern "C" void kernel_launch(void* const* d_in, const int* in_sizes, int n_in,
                              void* d_out, int out_size)
{
    const float* x = (const float*)d_in[0];
    const float* fea = (const float*)d_in[1];
    const float* im = (const float*)d_in[2];
    const float* Wq = (const float*)d_in[3];
    const float* Wk = (const float*)d_in[4];
    const float* Wv = (const float*)d_in[5];
    const float* rescale = (const float*)d_in[6];
    const float* Wp = (const float*)d_in[7];
    const float* bp = (const float*)d_in[8];
    const float* c1w = (const float*)d_in[9];
    const float* c2w = (const float*)d_in[10];
    float* out = (float*)d_out;

    cudaFuncSetAttribute(k4_conv_proj,
                         cudaFuncAttributeMaxDynamicSharedMemorySize, K4_SMEM);

    void* swptr = nullptr;
    cudaGetSymbolAddress(&swptr, g_SW);
    cudaMemsetAsync(swptr, 0, sizeof(float) * 2 * B * 24 * 64, 0);

    k1_kinp_S<<<dim3(128, B), 256>>>(x, im, Wk);
    k2_attn_W2<<<dim3(HEADS), 256>>>(Wq, Wv, Wp, rescale);
    k4_conv_proj<<<dim3(8, 16, B), 256, K4_SMEM>>>(fea, bp, c1w, c2w, out);
}